// round 13
// baseline (speedup 1.0000x reference)
#include <cuda_runtime.h>
#include <math.h>

#define Nn 512
#define CS 1024
#define CZ 128
#define Hh 12
#define HD 16
#define PQ 4
#define PV 8
#define CATD 2112   // 192 + 96*4 + 1536
#define NN (Nn*Nn)
#define PROJD 1152  // 192 + 384 + 144 + 432
#define QS 0.14433756729740643f   // sqrt(1/48)

typedef unsigned long long ull;

// ---------------- scratch (device globals; no allocation) ----------------
__device__ float g_proj[Nn*PROJD];
__device__ float g_qpts[Nn*Hh*PQ*3];      // [n][h][p][c]
__device__ ull   g_kT2[Hh*8*Nn];          // [h][dpair][j]
__device__ float g_vT[Hh*HD*Nn];          // [h][d][j]
__device__ ull   g_kpT2[Hh*6*Nn];         // [h][epair][j]
__device__ float g_vptsT[Hh*24*Nn];       // [h][p*3+c][j]
__device__ float g_knorm[Hh*Nn];          // [h][j] = sum kp^2
__device__ float g_bias[Hh*NN];           // [h][i][j], pre-scaled by sqrt(1/3)
__device__ float g_att[Hh*NN];
__device__ float g_opt[Nn*Hh*PV*3];
__device__ float g_cat[Nn*CATD];

// ---------------- f32x2 packed helpers ------------------------------------
__device__ __forceinline__ ull pk2(float x, float y) {
    ull r; asm("mov.b64 %0, {%1,%2};" : "=l"(r) : "f"(x), "f"(y)); return r;
}
__device__ __forceinline__ ull dup2(float x) {
    ull r; asm("mov.b64 %0, {%1,%1};" : "=l"(r) : "f"(x)); return r;
}
#define FMA2(c, a, b) asm("fma.rn.f32x2 %0, %1, %2, %0;" : "+l"(c) : "l"(a), "l"(b))
__device__ __forceinline__ void unpk2(ull v, float& lo, float& hi) {
    asm("mov.b64 {%0,%1}, %2;" : "=f"(lo), "=f"(hi) : "l"(v));
}
__device__ __forceinline__ float hadd2(ull v) {
    float lo, hi; unpk2(v, lo, hi); return lo + hi;
}

// ------- GEMM: BM=64,BN=64,BK=16, 256 thr, 4x4 f32x2; lda-aware, ACC ------
template<bool PROJ, bool ACC>
__global__ void __launch_bounds__(256)
gemm_kernel(const float* __restrict__ A,
            const float* __restrict__ W0,  const float* __restrict__ b0,
            const float* __restrict__ Wkv, const float* __restrict__ bkv,
            const float* __restrict__ Wqp, const float* __restrict__ bqp,
            const float* __restrict__ Wkvp,const float* __restrict__ bkvp,
            float* __restrict__ C, int Nd, int K, int lda) {
    __shared__ __align__(16) ull As2[16][64];   // [k][row] dup pairs {a,a}
    __shared__ __align__(16) ull Bs2[16][32];   // [k][colpair] {b0,b1}
    int tid = threadIdx.x;
    int m0 = blockIdx.y * 64, n0 = blockIdx.x * 64;
    int tx = tid & 15, ty = tid >> 4;

    int arow = tid >> 2, akb = (tid & 3) * 4;
    const float* Aptr = A + (size_t)(m0 + arow) * lda + akb;

    int lcol = n0 + tx * 4;
    const float* Bsrc; int ldw; int lc;
    if (PROJ) {
        if      (lcol < 192) { Bsrc = W0;   ldw = 192; lc = lcol;       }
        else if (lcol < 576) { Bsrc = Wkv;  ldw = 384; lc = lcol - 192; }
        else if (lcol < 720) { Bsrc = Wqp;  ldw = 144; lc = lcol - 576; }
        else                 { Bsrc = Wkvp; ldw = 432; lc = lcol - 720; }
    } else { Bsrc = W0; ldw = Nd; lc = lcol; }
    const float* Bptr = Bsrc + (size_t)ty * ldw + lc;

    float4 a4 = *(const float4*)Aptr;
    float4 b4 = *(const float4*)Bptr;

    ull acc[4][2];
    #pragma unroll
    for (int r = 0; r < 4; r++) { acc[r][0] = 0ull; acc[r][1] = 0ull; }

    int KT = K >> 4;
    for (int kt = 0; kt < KT; kt++) {
        __syncthreads();
        As2[akb + 0][arow] = dup2(a4.x);
        As2[akb + 1][arow] = dup2(a4.y);
        As2[akb + 2][arow] = dup2(a4.z);
        As2[akb + 3][arow] = dup2(a4.w);
        Bs2[ty][tx * 2]     = pk2(b4.x, b4.y);
        Bs2[ty][tx * 2 + 1] = pk2(b4.z, b4.w);
        __syncthreads();
        if (kt + 1 < KT) {
            a4 = *(const float4*)(Aptr + (kt + 1) * 16);
            b4 = *(const float4*)(Bptr + (size_t)(kt + 1) * 16 * ldw);
        }
        #pragma unroll
        for (int kk = 0; kk < 16; kk++) {
            ulonglong2 ap0 = *(const ulonglong2*)&As2[kk][ty * 4];
            ulonglong2 ap1 = *(const ulonglong2*)&As2[kk][ty * 4 + 2];
            ulonglong2 bp  = *(const ulonglong2*)&Bs2[kk][tx * 2];
            FMA2(acc[0][0], ap0.x, bp.x); FMA2(acc[0][1], ap0.x, bp.y);
            FMA2(acc[1][0], ap0.y, bp.x); FMA2(acc[1][1], ap0.y, bp.y);
            FMA2(acc[2][0], ap1.x, bp.x); FMA2(acc[2][1], ap1.x, bp.y);
            FMA2(acc[3][0], ap1.y, bp.x); FMA2(acc[3][1], ap1.y, bp.y);
        }
    }
    float4 bv = make_float4(0.f, 0.f, 0.f, 0.f);
    float scale = 1.f;
    if (!ACC) {
        const float* bsrc;
        if (PROJ) {
            if      (lcol < 192) { bsrc = b0;   scale = QS; }
            else if (lcol < 576) { bsrc = bkv; }
            else if (lcol < 720) { bsrc = bqp; }
            else                 { bsrc = bkvp; }
        } else { bsrc = b0; }
        int lcb = PROJ ? ((lcol < 192) ? lcol : (lcol < 576) ? lcol - 192
                           : (lcol < 720) ? lcol - 576 : lcol - 720) : lcol;
        bv = *(const float4*)(bsrc + lcb);
    }
    #pragma unroll
    for (int r = 0; r < 4; r++) {
        float* cp = C + (size_t)(m0 + ty * 4 + r) * Nd + n0 + tx * 4;
        float o0, o1, o2, o3;
        unpk2(acc[r][0], o0, o1);
        unpk2(acc[r][1], o2, o3);
        float4 o;
        if (ACC) {
            float4 cv = *(const float4*)cp;
            o.x = o0 + cv.x; o.y = o1 + cv.y; o.z = o2 + cv.z; o.w = o3 + cv.w;
        } else {
            o.x = (o0 + bv.x) * scale; o.y = (o1 + bv.y) * scale;
            o.z = (o2 + bv.z) * scale; o.w = (o3 + bv.w) * scale;
        }
        *(float4*)cp = o;
    }
}

// ------------- merged: point transforms + k/v repack (576 threads) --------
__global__ void __launch_bounds__(576)
pts_kernel(const float* __restrict__ rot,
           const float* __restrict__ trans) {
    int n = blockIdx.x;
    __shared__ float R[9], t3[3];
    __shared__ float kn[Hh][PQ];
    int tid = threadIdx.x;
    if (tid < 9) R[tid] = rot[n * 9 + tid];
    if (tid < 3) t3[tid] = trans[n * 3 + tid];
    __syncthreads();
    if (tid < 48) {
        int idx = tid;
        const float* raw = g_proj + n * PROJD + 576;
        float p0 = raw[idx], p1 = raw[48 + idx], p2 = raw[96 + idx];
        #pragma unroll
        for (int c = 0; c < 3; c++)
            g_qpts[n * 144 + idx * 3 + c] =
                R[c * 3] * p0 + R[c * 3 + 1] * p1 + R[c * 3 + 2] * p2 + t3[c];
    } else if (tid < 192) {
        int idx = tid - 48;
        const float* raw = g_proj + n * PROJD + 720;
        float p0 = raw[idx], p1 = raw[144 + idx], p2 = raw[288 + idx];
        int h = idx / 12, r = idx - h * 12;
        float o[3];
        #pragma unroll
        for (int c = 0; c < 3; c++)
            o[c] = R[c * 3] * p0 + R[c * 3 + 1] * p1 + R[c * 3 + 2] * p2 + t3[c];
        if (r < PQ) {
            float* fp = (float*)g_kpT2;
            #pragma unroll
            for (int c = 0; c < 3; c++) {
                int e = r * 3 + c;
                fp[((h * 6 + (e >> 1)) * Nn + n) * 2 + (e & 1)] = o[c];
            }
            kn[h][r] = o[0] * o[0] + o[1] * o[1] + o[2] * o[2];
        } else {
            int p = r - PQ;
            #pragma unroll
            for (int c = 0; c < 3; c++)
                g_vptsT[(h * 24 + p * 3 + c) * Nn + n] = o[c];
        }
    } else {
        int rt = tid - 192;   // 0..383 = h*32 + d
        float v = g_proj[n * PROJD + 192 + rt];
        int h = rt >> 5, d = rt & 31;
        if (d < 16) {
            float* fk = (float*)g_kT2;
            fk[((h * 8 + (d >> 1)) * Nn + n) * 2 + (d & 1)] = v;
        } else {
            g_vT[(h * 16 + d - 16) * Nn + n] = v;
        }
    }
    __syncthreads();
    if (tid < Hh)
        g_knorm[tid * Nn + n] = kn[tid][0] + kn[tid][1] + kn[tid][2] + kn[tid][3];
}

// ---------- bias: f32x2, double-buffered quarter-staged z -----------------
__global__ void __launch_bounds__(128)
bias_kernel(const float* __restrict__ z,
            const float* __restrict__ Wb,
            const float* __restrict__ bb) {
    int base = blockIdx.x * 128;
    __shared__ __align__(16) ull zs[2][128][17];
    __shared__ __align__(16) ull WbP[64][Hh];
    int tid = threadIdx.x;
    for (int t = tid; t < 64 * Hh; t += 128) {
        int cp = t / Hh, h = t - cp * Hh;
        WbP[cp][h] = pk2(Wb[(2 * cp) * Hh + h], Wb[(2 * cp + 1) * Hh + h]);
    }
    ull acc2[Hh];
    #pragma unroll
    for (int h = 0; h < Hh; h++) acc2[h] = 0ull;

    #pragma unroll
    for (int u = 0; u < 8; u++) {
        int t = tid + u * 128;
        int row = t >> 3, cc = (t & 7) * 4;
        float4 v = *(const float4*)&z[(size_t)(base + row) * CZ + cc];
        zs[0][row][cc >> 1]       = pk2(v.x, v.y);
        zs[0][row][(cc >> 1) + 1] = pk2(v.z, v.w);
    }
    #pragma unroll
    for (int q = 0; q < 4; q++) {
        __syncthreads();
        if (q < 3) {
            int nb = (q + 1) & 1;
            #pragma unroll
            for (int u = 0; u < 8; u++) {
                int t = tid + u * 128;
                int row = t >> 3, cc = (t & 7) * 4;
                float4 v = *(const float4*)&z[(size_t)(base + row) * CZ + (q + 1) * 32 + cc];
                zs[nb][row][cc >> 1]       = pk2(v.x, v.y);
                zs[nb][row][(cc >> 1) + 1] = pk2(v.z, v.w);
            }
        }
        int cb = q & 1;
        #pragma unroll
        for (int cl = 0; cl < 16; cl++) {
            ull zp = zs[cb][tid][cl];
            const ull* wp = &WbP[q * 16 + cl][0];
            #pragma unroll
            for (int hp = 0; hp < 6; hp++) {
                ulonglong2 w2 = *(const ulonglong2*)(wp + hp * 2);
                FMA2(acc2[2 * hp],     zp, w2.x);
                FMA2(acc2[2 * hp + 1], zp, w2.y);
            }
        }
    }
    int ij = base + tid;
    #pragma unroll
    for (int h = 0; h < Hh; h++)
        g_bias[h * NN + ij] = 0.5773502691896258f * (hadd2(acc2[h]) + bb[h]);
}

// ---------- attention logits + softmax, 4 rows/block, packed K loads ------
__global__ void __launch_bounds__(256)
attn_kernel(const float* __restrict__ head_w,
            const float* __restrict__ mask) {
    int h = blockIdx.x, i0 = blockIdx.y * 4;
    __shared__ __align__(16) float qv[4][16];
    __shared__ __align__(16) float qp[4][12];
    __shared__ float mi4[4], qn4[4];
    __shared__ float red[4][8];
    __shared__ float s_hw, s_res[4];
    int tid = threadIdx.x, lane = tid & 31, wid = tid >> 5;
    if (tid < 64) {
        int ii = tid >> 4, d = tid & 15;
        qv[ii][d] = g_proj[(i0 + ii) * PROJD + h * 16 + d];
    }
    if (tid < 48) {
        int ii = tid / 12, e = tid - ii * 12;
        qp[ii][e] = g_qpts[(i0 + ii) * 144 + h * 12 + e];
    }
    if (tid < 4) mi4[tid] = mask[i0 + tid];
    if (tid == 0) {
        float w = head_w[h];
        float sp = fmaxf(w, 0.f) + log1pf(__expf(-fabsf(w)));
        s_hw = sp * 0.5f * 0.13608276348795434f;   // 0.5*sqrt(1/54)
    }
    __syncthreads();
    if (tid < 4) {
        float s = 0.f;
        #pragma unroll
        for (int e = 0; e < 12; e++) s += qp[tid][e] * qp[tid][e];
        qn4[tid] = s;
    }
    __syncthreads();
    float hw = s_hw, hw2 = 2.f * s_hw;
    float logit[4][2];
    #pragma unroll
    for (int jj = 0; jj < 2; jj++) {
        int j = tid + jj * 256;
        ull kx2[8], kp2[6];
        #pragma unroll
        for (int d = 0; d < 8; d++) kx2[d] = g_kT2[(h * 8 + d) * Nn + j];
        #pragma unroll
        for (int e = 0; e < 6; e++) kp2[e] = g_kpT2[(h * 6 + e) * Nn + j];
        float kn = g_knorm[h * Nn + j];
        float mj = mask[j];
        #pragma unroll
        for (int ii = 0; ii < 4; ii++) {
            ull dk = 0ull, dp = 0ull;
            const ull* q2 = (const ull*)&qv[ii][0];
            const ull* p2 = (const ull*)&qp[ii][0];
            #pragma unroll
            for (int d = 0; d < 8; d++) FMA2(dk, q2[d], kx2[d]);
            #pragma unroll
            for (int e = 0; e < 6; e++) FMA2(dp, p2[e], kp2[e]);
            float dot = hadd2(dk), dpt = hadd2(dp);
            logit[ii][jj] = dot + g_bias[(h << 18) + ((i0 + ii) << 9) + j]
                          - hw * (qn4[ii] + kn) + hw2 * dpt
                          + 100000.0f * (mi4[ii] * mj - 1.0f);
        }
    }
    #pragma unroll
    for (int ii = 0; ii < 4; ii++) {
        float m = fmaxf(logit[ii][0], logit[ii][1]);
        #pragma unroll
        for (int o = 16; o > 0; o >>= 1) m = fmaxf(m, __shfl_xor_sync(0xffffffffu, m, o));
        if (lane == 0) red[ii][wid] = m;
    }
    __syncthreads();
    if (tid < 4) {
        float mm = red[tid][0];
        #pragma unroll
        for (int w = 1; w < 8; w++) mm = fmaxf(mm, red[tid][w]);
        s_res[tid] = mm;
    }
    __syncthreads();
    #pragma unroll
    for (int ii = 0; ii < 4; ii++) {
        float m = s_res[ii];
        logit[ii][0] = __expf(logit[ii][0] - m);
        logit[ii][1] = __expf(logit[ii][1] - m);
        float ss = logit[ii][0] + logit[ii][1];
        #pragma unroll
        for (int o = 16; o > 0; o >>= 1) ss += __shfl_xor_sync(0xffffffffu, ss, o);
        if (lane == 0) red[ii][wid] = ss;
    }
    __syncthreads();
    if (tid < 4) {
        float t = 0.f;
        #pragma unroll
        for (int w = 0; w < 8; w++) t += red[tid][w];
        s_res[tid] = 1.f / t;
    }
    __syncthreads();
    #pragma unroll
    for (int ii = 0; ii < 4; ii++) {
        float inv = s_res[ii];
        int o = (h << 18) + ((i0 + ii) << 9);
        g_att[o + tid]       = logit[ii][0] * inv;
        g_att[o + tid + 256] = logit[ii][1] * inv;
    }
}

// ---------- a@[v | v_pts] per head, 32-row tiles, coalesced loads ---------
__global__ void __launch_bounds__(320)
av_kernel() {
    int h = blockIdx.x;
    int i0 = blockIdx.y * 32;
    __shared__ __align__(16) float As[32][36];
    __shared__ __align__(16) float Vt[32][40];
    int tid = threadIdx.x;
    int tx = tid % 40, ty = tid / 40;
    float acc[4] = {};
    for (int k0 = 0; k0 < Nn; k0 += 32) {
        __syncthreads();
        for (int t = tid; t < 1024; t += 320) {
            int j = t & 31, ii = t >> 5;
            As[j][ii] = g_att[(h << 18) + ((i0 + ii) << 9) + k0 + j];
        }
        for (int t = tid; t < 1280; t += 320) {
            int col = t >> 5, row = t & 31;
            Vt[row][col] = (col < 16)
                ? g_vT[(h * 16 + col) * Nn + k0 + row]
                : g_vptsT[(h * 24 + col - 16) * Nn + k0 + row];
        }
        __syncthreads();
        #pragma unroll
        for (int j = 0; j < 32; j++) {
            float b = Vt[j][tx];
            float4 a = *(const float4*)&As[j][ty * 4];
            acc[0] += a.x * b; acc[1] += a.y * b;
            acc[2] += a.z * b; acc[3] += a.w * b;
        }
    }
    #pragma unroll
    for (int r = 0; r < 4; r++) {
        int i = i0 + ty * 4 + r;
        if (tx < 16) g_cat[(size_t)i * CATD + h * 16 + tx] = acc[r];
        else         g_opt[i * 288 + h * 24 + (tx - 16)]   = acc[r];
    }
}

// ---------- inverse frame transform + norm -> cat sections ----------------
__global__ void transform_kernel(const float* __restrict__ rot,
                                 const float* __restrict__ trans) {
    int n = blockIdx.x;
    __shared__ float R[9], t3[3];
    int tid = threadIdx.x;   // 128
    if (tid < 9) R[tid] = rot[n * 9 + tid];
    if (tid < 3) t3[tid] = trans[n * 3 + tid];
    __syncthreads();
    if (tid < 96) {
        int h = tid >> 3, p = tid & 7;
        int base = n * 288 + h * 24 + p * 3;
        float x = g_opt[base + 0] - t3[0];
        float y = g_opt[base + 1] - t3[1];
        float z = g_opt[base + 2] - t3[2];
        float lx = R[0] * x + R[3] * y + R[6] * z;
        float ly = R[1] * x + R[4] * y + R[7] * z;
        float lz = R[2] * x + R[5] * y + R[8] * z;
        size_t o = (size_t)n * CATD;
        int idx = h * 8 + p;
        g_cat[o + 192 + idx] = lx;
        g_cat[o + 288 + idx] = ly;
        g_cat[o + 384 + idx] = lz;
        g_cat[o + 480 + idx] = sqrtf(lx * lx + ly * ly + lz * lz + 1e-8f);
    }
}

// ---------- o_pair: f32x2 over j-pairs, MLP-8 z loads ---------------------
__global__ void __launch_bounds__(512)
opair_kernel(const float* __restrict__ z) {
    int i = blockIdx.x;
    __shared__ __align__(16) float as[Hh][520];
    int tid = threadIdx.x;
    int c = tid & 127, jq = tid >> 7;
    for (int t = tid; t < Hh * Nn; t += 512) {
        int h = t >> 9, j = t & 511;
        as[h][j] = g_att[(h << 18) + (i << 9) + j];
    }
    __syncthreads();
    ull acc2[Hh];
    #pragma unroll
    for (int h = 0; h < Hh; h++) acc2[h] = 0ull;
    const float* zrow = z + (size_t)i * Nn * CZ + c;
    int j0 = jq * 128;
    for (int j = j0; j < j0 + 128; j += 8) {
        float zr[8];
        #pragma unroll
        for (int u = 0; u < 8; u++) zr[u] = zrow[(size_t)(j + u) * CZ];
        ull zp0 = pk2(zr[0], zr[1]), zp1 = pk2(zr[2], zr[3]);
        ull zp2 = pk2(zr[4], zr[5]), zp3 = pk2(zr[6], zr[7]);
        #pragma unroll
        for (int h = 0; h < Hh; h++) {
            ulonglong2 a0 = *(const ulonglong2*)&as[h][j];
            ulonglong2 a1 = *(const ulonglong2*)&as[h][j + 4];
            FMA2(acc2[h], a0.x, zp0);
            FMA2(acc2[h], a0.y, zp1);
            FMA2(acc2[h], a1.x, zp2);
            FMA2(acc2[h], a1.y, zp3);
        }
    }
    __syncthreads();
    float* red = &as[0][0];
    if (jq > 0) {
        #pragma unroll
        for (int h = 0; h < Hh; h++)
            red[(jq - 1) * 1536 + h * 128 + c] = hadd2(acc2[h]);
    }
    __syncthreads();
    if (jq == 0) {
        size_t o = (size_t)i * CATD + 576;
        #pragma unroll
        for (int h = 0; h < Hh; h++) {
            float v = hadd2(acc2[h]) + red[h * 128 + c] + red[1536 + h * 128 + c]
                             + red[3072 + h * 128 + c];
            g_cat[o + h * CZ + c] = v;
        }
    }
}

// --------------------------------------------------------------------------
extern "C" void kernel_launch(void* const* d_in, const int* in_sizes, int n_in,
                              void* d_out, int out_size) {
    const float* s      = (const float*)d_in[0];
    const float* z      = (const float*)d_in[1];
    const float* rot    = (const float*)d_in[2];
    const float* trans  = (const float*)d_in[3];
    const float* mask   = (const float*)d_in[4];
    const float* Wq     = (const float*)d_in[5];
    const float* bq     = (const float*)d_in[6];
    const float* Wkv    = (const float*)d_in[7];
    const float* bkv    = (const float*)d_in[8];
    const float* Wqp    = (const float*)d_in[9];
    const float* bqp    = (const float*)d_in[10];
    const float* Wkvp   = (const float*)d_in[11];
    const float* bkvp   = (const float*)d_in[12];
    const float* Wb     = (const float*)d_in[13];
    const float* bb     = (const float*)d_in[14];
    const float* head_w = (const float*)d_in[15];
    const float* Wout   = (const float*)d_in[16];
    const float* bout   = (const float*)d_in[17];
    float* out = (float*)d_out;

    float *p_proj, *p_cat;
    cudaGetSymbolAddress((void**)&p_proj, g_proj);
    cudaGetSymbolAddress((void**)&p_cat,  g_cat);

    cudaStream_t sB;
    cudaStreamCreateWithFlags(&sB, cudaStreamNonBlocking);
    cudaEvent_t evFork, evBias, evAttn, evOpair;
    cudaEventCreateWithFlags(&evFork,  cudaEventDisableTiming);
    cudaEventCreateWithFlags(&evBias,  cudaEventDisableTiming);
    cudaEventCreateWithFlags(&evAttn,  cudaEventDisableTiming);
    cudaEventCreateWithFlags(&evOpair, cudaEventDisableTiming);

    // fork: bias depends only on inputs
    cudaEventRecord(evFork, 0);
    cudaStreamWaitEvent(sB, evFork, 0);
    bias_kernel<<<NN / 128, 128, 0, sB>>>(z, Wb, bb);
    cudaEventRecord(evBias, sB);

    // main chain
    gemm_kernel<true, false><<<dim3(PROJD / 64, Nn / 64), 256>>>(
        s, Wq, bq, Wkv, bkv, Wqp, bqp, Wkvp, bkvp, p_proj, PROJD, CS, CS);
    pts_kernel<<<Nn, 576>>>(rot, trans);
    cudaStreamWaitEvent(0, evBias, 0);          // join bias before attn
    attn_kernel<<<dim3(Hh, Nn / 4), 256>>>(head_w, mask);

    // fork: opair depends only on attn (+ z input)
    cudaEventRecord(evAttn, 0);
    cudaStreamWaitEvent(sB, evAttn, 0);
    opair_kernel<<<Nn, 512, 0, sB>>>(z);
    cudaEventRecord(evOpair, sB);

    av_kernel<<<dim3(Hh, Nn / 32), 320>>>();
    transform_kernel<<<Nn, 128>>>(rot, trans);

    // Wout part 1: cat columns [0, 576) — ready after av+transform; runs
    // concurrently with opair on the side stream. Includes the bias bout.
    gemm_kernel<false, false><<<dim3(CS / 64, Nn / 64), 256>>>(
        p_cat, Wout, bout, 0, 0, 0, 0, 0, 0, out, CS, 576, CATD);

    // Wout part 2: cat columns [576, 2112) — accumulates onto part 1.
    cudaStreamWaitEvent(0, evOpair, 0);         // join opair
    gemm_kernel<false, true><<<dim3(CS / 64, Nn / 64), 256>>>(
        p_cat + 576, Wout + (size_t)576 * CS, 0, 0, 0, 0, 0, 0, 0,
        out, CS, CATD - 576, CATD);

    cudaEventDestroy(evFork);
    cudaEventDestroy(evBias);
    cudaEventDestroy(evAttn);
    cudaEventDestroy(evOpair);
    cudaStreamDestroy(sB);
}

// round 14
// speedup vs baseline: 1.2847x; 1.2847x over previous
#include <cuda_runtime.h>
#include <math.h>

#define Nn 512
#define CS 1024
#define CZ 128
#define Hh 12
#define HD 16
#define PQ 4
#define PV 8
#define CATD 2112   // 192 + 96*4 + 1536
#define NN (Nn*Nn)
#define PROJD 1152  // 192 + 384 + 144 + 432
#define QS 0.14433756729740643f   // sqrt(1/48)

typedef unsigned long long ull;

// ---------------- scratch (device globals; no allocation) ----------------
__device__ float g_proj[Nn*PROJD];
__device__ float g_qpts[Nn*Hh*PQ*3];      // [n][h][p][c]
__device__ ull   g_kT2[Hh*8*Nn];          // [h][dpair][j]
__device__ float g_vT[Hh*HD*Nn];          // [h][d][j]
__device__ ull   g_kpT2[Hh*6*Nn];         // [h][epair][j]
__device__ float g_vptsT[Hh*24*Nn];       // [h][p*3+c][j]
__device__ float g_knorm[Hh*Nn];          // [h][j] = sum kp^2
__device__ float g_bias[Hh*NN];           // [h][i][j], pre-scaled by sqrt(1/3)
__device__ float g_att[Hh*NN];
__device__ float g_opt[Nn*Hh*PV*3];
__device__ float g_cat[Nn*CATD];

// ---------------- f32x2 packed helpers ------------------------------------
__device__ __forceinline__ ull pk2(float x, float y) {
    ull r; asm("mov.b64 %0, {%1,%2};" : "=l"(r) : "f"(x), "f"(y)); return r;
}
__device__ __forceinline__ ull dup2(float x) {
    ull r; asm("mov.b64 %0, {%1,%1};" : "=l"(r) : "f"(x)); return r;
}
#define FMA2(c, a, b) asm("fma.rn.f32x2 %0, %1, %2, %0;" : "+l"(c) : "l"(a), "l"(b))
__device__ __forceinline__ void unpk2(ull v, float& lo, float& hi) {
    asm("mov.b64 {%0,%1}, %2;" : "=f"(lo), "=f"(hi) : "l"(v));
}
__device__ __forceinline__ float hadd2(ull v) {
    float lo, hi; unpk2(v, lo, hi); return lo + hi;
}

// ------- GEMM (R12 known-good): BM=64,BN=64,BK=16, 256 thr, 4x4 f32x2 -----
template<bool PROJ>
__global__ void __launch_bounds__(256)
gemm_kernel(const float* __restrict__ A,
            const float* __restrict__ W0,  const float* __restrict__ b0,
            const float* __restrict__ Wkv, const float* __restrict__ bkv,
            const float* __restrict__ Wqp, const float* __restrict__ bqp,
            const float* __restrict__ Wkvp,const float* __restrict__ bkvp,
            float* __restrict__ C, int Nd, int K) {
    __shared__ __align__(16) ull As2[16][64];   // [k][row] dup pairs {a,a}
    __shared__ __align__(16) ull Bs2[16][32];   // [k][colpair] {b0,b1}
    int tid = threadIdx.x;
    int m0 = blockIdx.y * 64, n0 = blockIdx.x * 64;
    int tx = tid & 15, ty = tid >> 4;

    int arow = tid >> 2, akb = (tid & 3) * 4;
    const float* Aptr = A + (size_t)(m0 + arow) * K + akb;

    int lcol = n0 + tx * 4;
    const float* Bsrc; int ldw; int lc;
    if (PROJ) {
        if      (lcol < 192) { Bsrc = W0;   ldw = 192; lc = lcol;       }
        else if (lcol < 576) { Bsrc = Wkv;  ldw = 384; lc = lcol - 192; }
        else if (lcol < 720) { Bsrc = Wqp;  ldw = 144; lc = lcol - 576; }
        else                 { Bsrc = Wkvp; ldw = 432; lc = lcol - 720; }
    } else { Bsrc = W0; ldw = Nd; lc = lcol; }
    const float* Bptr = Bsrc + (size_t)ty * ldw + lc;

    float4 a4 = *(const float4*)Aptr;
    float4 b4 = *(const float4*)Bptr;

    ull acc[4][2];
    #pragma unroll
    for (int r = 0; r < 4; r++) { acc[r][0] = 0ull; acc[r][1] = 0ull; }

    int KT = K >> 4;
    for (int kt = 0; kt < KT; kt++) {
        __syncthreads();
        As2[akb + 0][arow] = dup2(a4.x);
        As2[akb + 1][arow] = dup2(a4.y);
        As2[akb + 2][arow] = dup2(a4.z);
        As2[akb + 3][arow] = dup2(a4.w);
        Bs2[ty][tx * 2]     = pk2(b4.x, b4.y);
        Bs2[ty][tx * 2 + 1] = pk2(b4.z, b4.w);
        __syncthreads();
        if (kt + 1 < KT) {
            a4 = *(const float4*)(Aptr + (kt + 1) * 16);
            b4 = *(const float4*)(Bptr + (size_t)(kt + 1) * 16 * ldw);
        }
        #pragma unroll
        for (int kk = 0; kk < 16; kk++) {
            ulonglong2 ap0 = *(const ulonglong2*)&As2[kk][ty * 4];
            ulonglong2 ap1 = *(const ulonglong2*)&As2[kk][ty * 4 + 2];
            ulonglong2 bp  = *(const ulonglong2*)&Bs2[kk][tx * 2];
            FMA2(acc[0][0], ap0.x, bp.x); FMA2(acc[0][1], ap0.x, bp.y);
            FMA2(acc[1][0], ap0.y, bp.x); FMA2(acc[1][1], ap0.y, bp.y);
            FMA2(acc[2][0], ap1.x, bp.x); FMA2(acc[2][1], ap1.x, bp.y);
            FMA2(acc[3][0], ap1.y, bp.x); FMA2(acc[3][1], ap1.y, bp.y);
        }
    }
    const float* bsrc; float scale;
    if (PROJ) {
        if      (lcol < 192) { bsrc = b0;   scale = QS; }
        else if (lcol < 576) { bsrc = bkv;  scale = 1.f; }
        else if (lcol < 720) { bsrc = bqp;  scale = 1.f; }
        else                 { bsrc = bkvp; scale = 1.f; }
    } else { bsrc = b0; scale = 1.f; }
    int lcb = PROJ ? ((lcol < 192) ? lcol : (lcol < 576) ? lcol - 192
                       : (lcol < 720) ? lcol - 576 : lcol - 720) : lcol;
    float4 bv = *(const float4*)(bsrc + lcb);
    #pragma unroll
    for (int r = 0; r < 4; r++) {
        float o0, o1, o2, o3;
        unpk2(acc[r][0], o0, o1);
        unpk2(acc[r][1], o2, o3);
        float4 o;
        o.x = (o0 + bv.x) * scale; o.y = (o1 + bv.y) * scale;
        o.z = (o2 + bv.z) * scale; o.w = (o3 + bv.w) * scale;
        *(float4*)(C + (size_t)(m0 + ty * 4 + r) * Nd + n0 + tx * 4) = o;
    }
}

// ------------- merged: point transforms + k/v repack (576 threads) --------
__global__ void __launch_bounds__(576)
pts_kernel(const float* __restrict__ rot,
           const float* __restrict__ trans) {
    int n = blockIdx.x;
    __shared__ float R[9], t3[3];
    __shared__ float kn[Hh][PQ];
    int tid = threadIdx.x;
    if (tid < 9) R[tid] = rot[n * 9 + tid];
    if (tid < 3) t3[tid] = trans[n * 3 + tid];
    __syncthreads();
    if (tid < 48) {
        int idx = tid;
        const float* raw = g_proj + n * PROJD + 576;
        float p0 = raw[idx], p1 = raw[48 + idx], p2 = raw[96 + idx];
        #pragma unroll
        for (int c = 0; c < 3; c++)
            g_qpts[n * 144 + idx * 3 + c] =
                R[c * 3] * p0 + R[c * 3 + 1] * p1 + R[c * 3 + 2] * p2 + t3[c];
    } else if (tid < 192) {
        int idx = tid - 48;
        const float* raw = g_proj + n * PROJD + 720;
        float p0 = raw[idx], p1 = raw[144 + idx], p2 = raw[288 + idx];
        int h = idx / 12, r = idx - h * 12;
        float o[3];
        #pragma unroll
        for (int c = 0; c < 3; c++)
            o[c] = R[c * 3] * p0 + R[c * 3 + 1] * p1 + R[c * 3 + 2] * p2 + t3[c];
        if (r < PQ) {
            float* fp = (float*)g_kpT2;
            #pragma unroll
            for (int c = 0; c < 3; c++) {
                int e = r * 3 + c;
                fp[((h * 6 + (e >> 1)) * Nn + n) * 2 + (e & 1)] = o[c];
            }
            kn[h][r] = o[0] * o[0] + o[1] * o[1] + o[2] * o[2];
        } else {
            int p = r - PQ;
            #pragma unroll
            for (int c = 0; c < 3; c++)
                g_vptsT[(h * 24 + p * 3 + c) * Nn + n] = o[c];
        }
    } else {
        int rt = tid - 192;   // 0..383 = h*32 + d
        float v = g_proj[n * PROJD + 192 + rt];
        int h = rt >> 5, d = rt & 31;
        if (d < 16) {
            float* fk = (float*)g_kT2;
            fk[((h * 8 + (d >> 1)) * Nn + n) * 2 + (d & 1)] = v;
        } else {
            g_vT[(h * 16 + d - 16) * Nn + n] = v;
        }
    }
    __syncthreads();
    if (tid < Hh)
        g_knorm[tid * Nn + n] = kn[tid][0] + kn[tid][1] + kn[tid][2] + kn[tid][3];
}

// ---------- bias: f32x2, double-buffered quarter-staged z -----------------
__global__ void __launch_bounds__(128)
bias_kernel(const float* __restrict__ z,
            const float* __restrict__ Wb,
            const float* __restrict__ bb) {
    int base = blockIdx.x * 128;
    __shared__ __align__(16) ull zs[2][128][17];
    __shared__ __align__(16) ull WbP[64][Hh];
    int tid = threadIdx.x;
    for (int t = tid; t < 64 * Hh; t += 128) {
        int cp = t / Hh, h = t - cp * Hh;
        WbP[cp][h] = pk2(Wb[(2 * cp) * Hh + h], Wb[(2 * cp + 1) * Hh + h]);
    }
    ull acc2[Hh];
    #pragma unroll
    for (int h = 0; h < Hh; h++) acc2[h] = 0ull;

    #pragma unroll
    for (int u = 0; u < 8; u++) {
        int t = tid + u * 128;
        int row = t >> 3, cc = (t & 7) * 4;
        float4 v = *(const float4*)&z[(size_t)(base + row) * CZ + cc];
        zs[0][row][cc >> 1]       = pk2(v.x, v.y);
        zs[0][row][(cc >> 1) + 1] = pk2(v.z, v.w);
    }
    #pragma unroll
    for (int q = 0; q < 4; q++) {
        __syncthreads();
        if (q < 3) {
            int nb = (q + 1) & 1;
            #pragma unroll
            for (int u = 0; u < 8; u++) {
                int t = tid + u * 128;
                int row = t >> 3, cc = (t & 7) * 4;
                float4 v = *(const float4*)&z[(size_t)(base + row) * CZ + (q + 1) * 32 + cc];
                zs[nb][row][cc >> 1]       = pk2(v.x, v.y);
                zs[nb][row][(cc >> 1) + 1] = pk2(v.z, v.w);
            }
        }
        int cb = q & 1;
        #pragma unroll
        for (int cl = 0; cl < 16; cl++) {
            ull zp = zs[cb][tid][cl];
            const ull* wp = &WbP[q * 16 + cl][0];
            #pragma unroll
            for (int hp = 0; hp < 6; hp++) {
                ulonglong2 w2 = *(const ulonglong2*)(wp + hp * 2);
                FMA2(acc2[2 * hp],     zp, w2.x);
                FMA2(acc2[2 * hp + 1], zp, w2.y);
            }
        }
    }
    int ij = base + tid;
    #pragma unroll
    for (int h = 0; h < Hh; h++)
        g_bias[h * NN + ij] = 0.5773502691896258f * (hadd2(acc2[h]) + bb[h]);
}

// ---------- attention logits + softmax, 4 rows/block, packed K loads ------
__global__ void __launch_bounds__(256)
attn_kernel(const float* __restrict__ head_w,
            const float* __restrict__ mask) {
    int h = blockIdx.x, i0 = blockIdx.y * 4;
    __shared__ __align__(16) float qv[4][16];
    __shared__ __align__(16) float qp[4][12];
    __shared__ float mi4[4], qn4[4];
    __shared__ float red[4][8];
    __shared__ float s_hw, s_res[4];
    int tid = threadIdx.x, lane = tid & 31, wid = tid >> 5;
    if (tid < 64) {
        int ii = tid >> 4, d = tid & 15;
        qv[ii][d] = g_proj[(i0 + ii) * PROJD + h * 16 + d];
    }
    if (tid < 48) {
        int ii = tid / 12, e = tid - ii * 12;
        qp[ii][e] = g_qpts[(i0 + ii) * 144 + h * 12 + e];
    }
    if (tid < 4) mi4[tid] = mask[i0 + tid];
    if (tid == 0) {
        float w = head_w[h];
        float sp = fmaxf(w, 0.f) + log1pf(__expf(-fabsf(w)));
        s_hw = sp * 0.5f * 0.13608276348795434f;   // 0.5*sqrt(1/54)
    }
    __syncthreads();
    if (tid < 4) {
        float s = 0.f;
        #pragma unroll
        for (int e = 0; e < 12; e++) s += qp[tid][e] * qp[tid][e];
        qn4[tid] = s;
    }
    __syncthreads();
    float hw = s_hw, hw2 = 2.f * s_hw;
    float logit[4][2];
    #pragma unroll
    for (int jj = 0; jj < 2; jj++) {
        int j = tid + jj * 256;
        ull kx2[8], kp2[6];
        #pragma unroll
        for (int d = 0; d < 8; d++) kx2[d] = g_kT2[(h * 8 + d) * Nn + j];
        #pragma unroll
        for (int e = 0; e < 6; e++) kp2[e] = g_kpT2[(h * 6 + e) * Nn + j];
        float kn = g_knorm[h * Nn + j];
        float mj = mask[j];
        #pragma unroll
        for (int ii = 0; ii < 4; ii++) {
            ull dk = 0ull, dp = 0ull;
            const ull* q2 = (const ull*)&qv[ii][0];
            const ull* p2 = (const ull*)&qp[ii][0];
            #pragma unroll
            for (int d = 0; d < 8; d++) FMA2(dk, q2[d], kx2[d]);
            #pragma unroll
            for (int e = 0; e < 6; e++) FMA2(dp, p2[e], kp2[e]);
            float dot = hadd2(dk), dpt = hadd2(dp);
            logit[ii][jj] = dot + g_bias[(h << 18) + ((i0 + ii) << 9) + j]
                          - hw * (qn4[ii] + kn) + hw2 * dpt
                          + 100000.0f * (mi4[ii] * mj - 1.0f);
        }
    }
    #pragma unroll
    for (int ii = 0; ii < 4; ii++) {
        float m = fmaxf(logit[ii][0], logit[ii][1]);
        #pragma unroll
        for (int o = 16; o > 0; o >>= 1) m = fmaxf(m, __shfl_xor_sync(0xffffffffu, m, o));
        if (lane == 0) red[ii][wid] = m;
    }
    __syncthreads();
    if (tid < 4) {
        float mm = red[tid][0];
        #pragma unroll
        for (int w = 1; w < 8; w++) mm = fmaxf(mm, red[tid][w]);
        s_res[tid] = mm;
    }
    __syncthreads();
    #pragma unroll
    for (int ii = 0; ii < 4; ii++) {
        float m = s_res[ii];
        logit[ii][0] = __expf(logit[ii][0] - m);
        logit[ii][1] = __expf(logit[ii][1] - m);
        float ss = logit[ii][0] + logit[ii][1];
        #pragma unroll
        for (int o = 16; o > 0; o >>= 1) ss += __shfl_xor_sync(0xffffffffu, ss, o);
        if (lane == 0) red[ii][wid] = ss;
    }
    __syncthreads();
    if (tid < 4) {
        float t = 0.f;
        #pragma unroll
        for (int w = 0; w < 8; w++) t += red[tid][w];
        s_res[tid] = 1.f / t;
    }
    __syncthreads();
    #pragma unroll
    for (int ii = 0; ii < 4; ii++) {
        float inv = s_res[ii];
        int o = (h << 18) + ((i0 + ii) << 9);
        g_att[o + tid]       = logit[ii][0] * inv;
        g_att[o + tid + 256] = logit[ii][1] * inv;
    }
}

// ---------- a@[v | v_pts] per head, 32-row tiles, coalesced loads ---------
__global__ void __launch_bounds__(320)
av_kernel() {
    int h = blockIdx.x;
    int i0 = blockIdx.y * 32;
    __shared__ __align__(16) float As[32][36];
    __shared__ __align__(16) float Vt[32][40];
    int tid = threadIdx.x;
    int tx = tid % 40, ty = tid / 40;
    float acc[4] = {};
    for (int k0 = 0; k0 < Nn; k0 += 32) {
        __syncthreads();
        for (int t = tid; t < 1024; t += 320) {
            int j = t & 31, ii = t >> 5;
            As[j][ii] = g_att[(h << 18) + ((i0 + ii) << 9) + k0 + j];
        }
        for (int t = tid; t < 1280; t += 320) {
            int col = t >> 5, row = t & 31;
            Vt[row][col] = (col < 16)
                ? g_vT[(h * 16 + col) * Nn + k0 + row]
                : g_vptsT[(h * 24 + col - 16) * Nn + k0 + row];
        }
        __syncthreads();
        #pragma unroll
        for (int j = 0; j < 32; j++) {
            float b = Vt[j][tx];
            float4 a = *(const float4*)&As[j][ty * 4];
            acc[0] += a.x * b; acc[1] += a.y * b;
            acc[2] += a.z * b; acc[3] += a.w * b;
        }
    }
    #pragma unroll
    for (int r = 0; r < 4; r++) {
        int i = i0 + ty * 4 + r;
        if (tx < 16) g_cat[(size_t)i * CATD + h * 16 + tx] = acc[r];
        else         g_opt[i * 288 + h * 24 + (tx - 16)]   = acc[r];
    }
}

// ---------- inverse frame transform + norm -> cat sections ----------------
__global__ void transform_kernel(const float* __restrict__ rot,
                                 const float* __restrict__ trans) {
    int n = blockIdx.x;
    __shared__ float R[9], t3[3];
    int tid = threadIdx.x;   // 128
    if (tid < 9) R[tid] = rot[n * 9 + tid];
    if (tid < 3) t3[tid] = trans[n * 3 + tid];
    __syncthreads();
    if (tid < 96) {
        int h = tid >> 3, p = tid & 7;
        int base = n * 288 + h * 24 + p * 3;
        float x = g_opt[base + 0] - t3[0];
        float y = g_opt[base + 1] - t3[1];
        float z = g_opt[base + 2] - t3[2];
        float lx = R[0] * x + R[3] * y + R[6] * z;
        float ly = R[1] * x + R[4] * y + R[7] * z;
        float lz = R[2] * x + R[5] * y + R[8] * z;
        size_t o = (size_t)n * CATD;
        int idx = h * 8 + p;
        g_cat[o + 192 + idx] = lx;
        g_cat[o + 288 + idx] = ly;
        g_cat[o + 384 + idx] = lz;
        g_cat[o + 480 + idx] = sqrtf(lx * lx + ly * ly + lz * lz + 1e-8f);
    }
}

// ---------- o_pair: f32x2 over j-pairs, MLP-8 z loads ---------------------
__global__ void __launch_bounds__(512)
opair_kernel(const float* __restrict__ z) {
    int i = blockIdx.x;
    __shared__ __align__(16) float as[Hh][520];
    int tid = threadIdx.x;
    int c = tid & 127, jq = tid >> 7;
    for (int t = tid; t < Hh * Nn; t += 512) {
        int h = t >> 9, j = t & 511;
        as[h][j] = g_att[(h << 18) + (i << 9) + j];
    }
    __syncthreads();
    ull acc2[Hh];
    #pragma unroll
    for (int h = 0; h < Hh; h++) acc2[h] = 0ull;
    const float* zrow = z + (size_t)i * Nn * CZ + c;
    int j0 = jq * 128;
    for (int j = j0; j < j0 + 128; j += 8) {
        float zr[8];
        #pragma unroll
        for (int u = 0; u < 8; u++) zr[u] = zrow[(size_t)(j + u) * CZ];
        ull zp0 = pk2(zr[0], zr[1]), zp1 = pk2(zr[2], zr[3]);
        ull zp2 = pk2(zr[4], zr[5]), zp3 = pk2(zr[6], zr[7]);
        #pragma unroll
        for (int h = 0; h < Hh; h++) {
            ulonglong2 a0 = *(const ulonglong2*)&as[h][j];
            ulonglong2 a1 = *(const ulonglong2*)&as[h][j + 4];
            FMA2(acc2[h], a0.x, zp0);
            FMA2(acc2[h], a0.y, zp1);
            FMA2(acc2[h], a1.x, zp2);
            FMA2(acc2[h], a1.y, zp3);
        }
    }
    __syncthreads();
    float* red = &as[0][0];
    if (jq > 0) {
        #pragma unroll
        for (int h = 0; h < Hh; h++)
            red[(jq - 1) * 1536 + h * 128 + c] = hadd2(acc2[h]);
    }
    __syncthreads();
    if (jq == 0) {
        size_t o = (size_t)i * CATD + 576;
        #pragma unroll
        for (int h = 0; h < Hh; h++) {
            float v = hadd2(acc2[h]) + red[h * 128 + c] + red[1536 + h * 128 + c]
                             + red[3072 + h * 128 + c];
            g_cat[o + h * CZ + c] = v;
        }
    }
}

// --------------------------------------------------------------------------
extern "C" void kernel_launch(void* const* d_in, const int* in_sizes, int n_in,
                              void* d_out, int out_size) {
    const float* s      = (const float*)d_in[0];
    const float* z      = (const float*)d_in[1];
    const float* rot    = (const float*)d_in[2];
    const float* trans  = (const float*)d_in[3];
    const float* mask   = (const float*)d_in[4];
    const float* Wq     = (const float*)d_in[5];
    const float* bq     = (const float*)d_in[6];
    const float* Wkv    = (const float*)d_in[7];
    const float* bkv    = (const float*)d_in[8];
    const float* Wqp    = (const float*)d_in[9];
    const float* bqp    = (const float*)d_in[10];
    const float* Wkvp   = (const float*)d_in[11];
    const float* bkvp   = (const float*)d_in[12];
    const float* Wb     = (const float*)d_in[13];
    const float* bb     = (const float*)d_in[14];
    const float* head_w = (const float*)d_in[15];
    const float* Wout   = (const float*)d_in[16];
    const float* bout   = (const float*)d_in[17];
    float* out = (float*)d_out;

    float *p_proj, *p_cat;
    cudaGetSymbolAddress((void**)&p_proj, g_proj);
    cudaGetSymbolAddress((void**)&p_cat,  g_cat);

    cudaStream_t sB;
    cudaStreamCreateWithFlags(&sB, cudaStreamNonBlocking);
    cudaEvent_t evFork, evBias, evAttn, evOpair;
    cudaEventCreateWithFlags(&evFork,  cudaEventDisableTiming);
    cudaEventCreateWithFlags(&evBias,  cudaEventDisableTiming);
    cudaEventCreateWithFlags(&evAttn,  cudaEventDisableTiming);
    cudaEventCreateWithFlags(&evOpair, cudaEventDisableTiming);

    // fork: bias depends only on inputs
    cudaEventRecord(evFork, 0);
    cudaStreamWaitEvent(sB, evFork, 0);
    bias_kernel<<<NN / 128, 128, 0, sB>>>(z, Wb, bb);
    cudaEventRecord(evBias, sB);

    // main chain
    gemm_kernel<true><<<dim3(PROJD / 64, Nn / 64), 256>>>(
        s, Wq, bq, Wkv, bkv, Wqp, bqp, Wkvp, bkvp, p_proj, PROJD, CS);
    pts_kernel<<<Nn, 576>>>(rot, trans);
    cudaStreamWaitEvent(0, evBias, 0);          // join bias before attn
    attn_kernel<<<dim3(Hh, Nn / 4), 256>>>(head_w, mask);

    // fork: opair depends only on attn (+ z input)
    cudaEventRecord(evAttn, 0);
    cudaStreamWaitEvent(sB, evAttn, 0);
    opair_kernel<<<Nn, 512, 0, sB>>>(z);
    cudaEventRecord(evOpair, sB);

    av_kernel<<<dim3(Hh, Nn / 32), 320>>>();
    transform_kernel<<<Nn, 128>>>(rot, trans);
    cudaStreamWaitEvent(0, evOpair, 0);         // join opair before Wout
    gemm_kernel<false><<<dim3(CS / 64, Nn / 64), 256>>>(
        p_cat, Wout, bout, 0, 0, 0, 0, 0, 0, out, CS, CATD);

    cudaEventDestroy(evFork);
    cudaEventDestroy(evBias);
    cudaEventDestroy(evAttn);
    cudaEventDestroy(evOpair);
    cudaStreamDestroy(sB);
}